// round 3
// baseline (speedup 1.0000x reference)
#include <cuda_runtime.h>
#include <cuda_bf16.h>
#include <math.h>

#define H 512
#define W 512
#define B 32
#define CELL 16
#define NC 32            // cells per dim
#define NB 31            // blocks per dim
#define ORI 6
#define BLK_FEAT 24      // 2*2*ORI
#define HWsz (H*W)

// scratch: per-cell histograms, (B, 32, 32, 6)
__device__ float g_cells[B * NC * NC * ORI];

// ---------------------------------------------------------------------------
// Kernel A: strip-based. One 512-thread CTA per (image, cell-row).
// Phase 1: float4-vectorized coalesced load of 18 gray rows into smem.
// Phase 2: central-difference gradients, orientation binning via cross-product
// sign tests, register-resident 6-bin histograms, 16-lane shfl reduction.
// ---------------------------------------------------------------------------
__global__ __launch_bounds__(512) void hog_cells_kernel(
    const float* __restrict__ x, float* __restrict__ cells)
{
    const int strip = blockIdx.x;   // cell row 0..31
    const int b     = blockIdx.y;   // image

    __shared__ float sm[18][512];

    const int tid = threadIdx.x;
    const float* xb = x + (size_t)b * 3 * HWsz;
    const int r0 = strip * CELL - 1;

    // Phase 1: 18 rows x 128 float4-slots = 2304 slots, 512 threads -> 4.5 iters
    #pragma unroll
    for (int it = 0; it < 5; it++) {
        const int idx = tid + it * 512;
        if (idx < 18 * 128) {
            const int i = idx >> 7;          // row 0..17
            const int j = idx & 127;         // float4 col
            const int r = r0 + i;
            float4 g4 = make_float4(0.f, 0.f, 0.f, 0.f);
            if (r >= 0 && r < H) {
                const float4* base = (const float4*)(xb + r * W) + j;
                const float4 R = __ldg(base);
                const float4 G = __ldg(base + (HWsz >> 2));
                const float4 Bc = __ldg(base + (HWsz >> 1));
                g4.x = 0.299f * R.x + 0.587f * G.x + 0.114f * Bc.x;
                g4.y = 0.299f * R.y + 0.587f * G.y + 0.114f * Bc.y;
                g4.z = 0.299f * R.z + 0.587f * G.z + 0.114f * Bc.z;
                g4.w = 0.299f * R.w + 0.587f * G.w + 0.114f * Bc.w;
            }
            *((float4*)&sm[i][j << 2]) = g4;
        }
    }
    __syncthreads();

    // Phase 2: gradients + binning, one column per thread
    const int c = tid;
    float h0 = 0.f, h1 = 0.f, h2 = 0.f, h3 = 0.f, h4 = 0.f, h5 = 0.f;

    const bool cok = (c > 0) && (c < W - 1);
    const float C30 = 0.8660254037844386f;  // cos 30

    #pragma unroll
    for (int i = 0; i < 16; i++) {
        const int r = strip * CELL + i;
        const float gr = (r > 0 && r < H - 1) ? sm[i + 2][c] - sm[i][c] : 0.0f;
        const float gc = cok ? sm[i + 1][c + 1] - sm[i + 1][c - 1] : 0.0f;

        const float mag = sqrtf(gr * gr + gc * gc);

        // bin = floor((degrees(atan2(gr,gc)) mod 180)/30) via boundary tests
        float X = gc, Y = gr;
        if (Y < 0.0f || (Y == 0.0f && X < 0.0f)) { X = -X; Y = -Y; }
        int bin = 0;
        bin += (C30  * Y - 0.5f * X >= 0.0f);   // >= 30 deg
        bin += (0.5f * Y - C30  * X >= 0.0f);   // >= 60
        bin += (          -        X >= 0.0f);  // >= 90
        bin += (-0.5f * Y - C30 * X >= 0.0f);   // >= 120
        bin += (-C30  * Y - 0.5f * X >= 0.0f);  // >= 150

        h0 += (bin == 0) ? mag : 0.0f;
        h1 += (bin == 1) ? mag : 0.0f;
        h2 += (bin == 2) ? mag : 0.0f;
        h3 += (bin == 3) ? mag : 0.0f;
        h4 += (bin == 4) ? mag : 0.0f;
        h5 += (bin == 5) ? mag : 0.0f;
    }

    #pragma unroll
    for (int s = 8; s; s >>= 1) {
        h0 += __shfl_xor_sync(0xffffffffu, h0, s);
        h1 += __shfl_xor_sync(0xffffffffu, h1, s);
        h2 += __shfl_xor_sync(0xffffffffu, h2, s);
        h3 += __shfl_xor_sync(0xffffffffu, h3, s);
        h4 += __shfl_xor_sync(0xffffffffu, h4, s);
        h5 += __shfl_xor_sync(0xffffffffu, h5, s);
    }

    if ((c & 15) == 0) {
        const int cellx = c >> 4;
        float* dst = cells + (((size_t)b * NC + strip) * NC + cellx) * ORI;
        const float inv = 1.0f / (CELL * CELL);
        dst[0] = h0 * inv;
        dst[1] = h1 * inv;
        dst[2] = h2 * inv;
        dst[3] = h3 * inv;
        dst[4] = h4 * inv;
        dst[5] = h5 * inv;
    }
}

// ---------------------------------------------------------------------------
// Kernel B: 8 lanes per HOG block (246k threads). Each lane holds 3 of the
// 24 block values; two 3-step shfl reductions for the L2-Hys norms.
// ---------------------------------------------------------------------------
__global__ __launch_bounds__(256) void hog_blocks_kernel(
    const float* __restrict__ cells, float* __restrict__ out)
{
    const int t = blockIdx.x * blockDim.x + threadIdx.x;
    const int g = t >> 3;           // HOG block index
    const int l = t & 7;            // lane within group
    const int total = B * NB * NB;
    if (g >= total) return;

    const int b  = g / (NB * NB);
    const int ij = g - b * (NB * NB);
    const int i  = ij / NB;
    const int j  = ij - i * NB;

    // lanes 0-3: cell row i (12 contiguous floats); lanes 4-7: row i+1
    const int row = i + (l >> 2);
    const int off = (l & 3) * 3;
    const float* p = cells + (((size_t)b * NC + row) * NC + j) * ORI + off;

    float v0 = __ldg(p);
    float v1 = __ldg(p + 1);
    float v2 = __ldg(p + 2);

    const float EPS2 = 1e-10f;  // (1e-5)^2

    float ss = v0 * v0 + v1 * v1 + v2 * v2;
    #pragma unroll
    for (int s = 4; s; s >>= 1) ss += __shfl_xor_sync(0xffffffffu, ss, s);
    const float inv_n1 = rsqrtf(ss + EPS2) * sqrtf((ss + EPS2) * (1.0f / (ss + EPS2)));
    // (use plain 1/sqrt for exactness w.r.t. reference tolerance)
    const float n1 = sqrtf(ss + EPS2);
    v0 = fminf(v0 / n1, 0.2f);
    v1 = fminf(v1 / n1, 0.2f);
    v2 = fminf(v2 / n1, 0.2f);

    float ss2 = v0 * v0 + v1 * v1 + v2 * v2;
    #pragma unroll
    for (int s = 4; s; s >>= 1) ss2 += __shfl_xor_sync(0xffffffffu, ss2, s);
    const float n2 = sqrtf(ss2 + EPS2);

    float* o = out + (size_t)g * BLK_FEAT + l * 3;
    o[0] = v0 / n2;
    o[1] = v1 / n2;
    o[2] = v2 / n2;
    (void)inv_n1;
}

// ---------------------------------------------------------------------------
extern "C" void kernel_launch(void* const* d_in, const int* in_sizes, int n_in,
                              void* d_out, int out_size)
{
    const float* x = (const float*)d_in[0];
    float* out = (float*)d_out;

    float* cells;
    cudaGetSymbolAddress((void**)&cells, g_cells);

    dim3 gridA(NC, B);
    hog_cells_kernel<<<gridA, 512>>>(x, cells);

    const int total = B * NB * NB;                 // 30752
    const int threadsB = total * 8;
    hog_blocks_kernel<<<(threadsB + 255) / 256, 256>>>(cells, out);
}

// round 4
// speedup vs baseline: 1.0626x; 1.0626x over previous
#include <cuda_runtime.h>
#include <cuda_bf16.h>
#include <math.h>

#define H 512
#define W 512
#define B 32
#define CELL 16
#define NC 32            // cells per dim
#define NB 31            // blocks per dim
#define ORI 6
#define BLK_FEAT 24      // 2*2*ORI
#define HWsz (H*W)
#define NSTRIPS (B * NC) // 1024 jobs
#define GRID_A 592       // 148 SMs * 4 CTAs/SM (512thr, 36KB smem)

// scratch: per-cell histograms, (B, 32, 32, 6)
__device__ float g_cells[B * NC * NC * ORI];

// ---------------------------------------------------------------------------
// Kernel A: persistent strip CTAs. Each 512-thread CTA grid-strides over
// (image, cell-row) jobs. Scalar coalesced loads (R2 form — fastest measured),
// 18x512 smem gray strip, register histograms, 16-lane shfl reduction.
// ---------------------------------------------------------------------------
__global__ __launch_bounds__(512) void hog_cells_kernel(
    const float* __restrict__ x, float* __restrict__ cells)
{
    __shared__ float sm[18][512];
    const int c = threadIdx.x;      // column 0..511
    const bool cok = (c > 0) && (c < W - 1);
    const float C30 = 0.8660254037844386f;  // cos 30

    for (int job = blockIdx.x; job < NSTRIPS; job += GRID_A) {
        const int strip = job & (NC - 1);   // cell row 0..31
        const int b     = job >> 5;         // image

        const float* xb = x + (size_t)b * 3 * HWsz;
        const int r0 = strip * CELL - 1;

        __syncthreads();   // protect smem from previous iteration's readers

        // load 18 rows of grayscale (OOB rows -> 0), fully coalesced
        #pragma unroll
        for (int i = 0; i < 18; i++) {
            const int r = r0 + i;
            float g = 0.0f;
            if (r >= 0 && r < H) {
                const int p = r * W + c;
                g = 0.299f * __ldg(xb + p)
                  + 0.587f * __ldg(xb + HWsz + p)
                  + 0.114f * __ldg(xb + 2 * HWsz + p);
            }
            sm[i][c] = g;
        }
        __syncthreads();

        float h0 = 0.f, h1 = 0.f, h2 = 0.f, h3 = 0.f, h4 = 0.f, h5 = 0.f;

        #pragma unroll
        for (int i = 0; i < 16; i++) {
            const int r = strip * CELL + i;
            // central differences with zeroed borders (skimage semantics)
            const float gr = (r > 0 && r < H - 1) ? sm[i + 2][c] - sm[i][c] : 0.0f;
            const float gc = cok ? sm[i + 1][c + 1] - sm[i + 1][c - 1] : 0.0f;

            const float mag = sqrtf(gr * gr + gc * gc);

            // bin = floor((degrees(atan2(gr,gc)) mod 180)/30) via boundary
            // cross-product sign tests after canonicalizing to upper half-plane
            float X = gc, Y = gr;
            if (Y < 0.0f || (Y == 0.0f && X < 0.0f)) { X = -X; Y = -Y; }
            int bin = 0;
            bin += (C30  * Y - 0.5f * X >= 0.0f);   // >= 30 deg
            bin += (0.5f * Y - C30  * X >= 0.0f);   // >= 60
            bin += (          -        X >= 0.0f);  // >= 90
            bin += (-0.5f * Y - C30 * X >= 0.0f);   // >= 120
            bin += (-C30  * Y - 0.5f * X >= 0.0f);  // >= 150

            h0 += (bin == 0) ? mag : 0.0f;
            h1 += (bin == 1) ? mag : 0.0f;
            h2 += (bin == 2) ? mag : 0.0f;
            h3 += (bin == 3) ? mag : 0.0f;
            h4 += (bin == 4) ? mag : 0.0f;
            h5 += (bin == 5) ? mag : 0.0f;
        }

        // reduce across the 16 lanes of each column group
        #pragma unroll
        for (int s = 8; s; s >>= 1) {
            h0 += __shfl_xor_sync(0xffffffffu, h0, s);
            h1 += __shfl_xor_sync(0xffffffffu, h1, s);
            h2 += __shfl_xor_sync(0xffffffffu, h2, s);
            h3 += __shfl_xor_sync(0xffffffffu, h3, s);
            h4 += __shfl_xor_sync(0xffffffffu, h4, s);
            h5 += __shfl_xor_sync(0xffffffffu, h5, s);
        }

        if ((c & 15) == 0) {
            const int cellx = c >> 4;
            float* dst = cells + (((size_t)b * NC + strip) * NC + cellx) * ORI;
            const float inv = 1.0f / (CELL * CELL);
            dst[0] = h0 * inv;
            dst[1] = h1 * inv;
            dst[2] = h2 * inv;
            dst[3] = h3 * inv;
            dst[4] = h4 * inv;
            dst[5] = h5 * inv;
        }
    }
}

// ---------------------------------------------------------------------------
// Kernel B: 8 lanes per HOG block; rsqrt-based L2-Hys (short dep chain).
// ---------------------------------------------------------------------------
__global__ __launch_bounds__(256) void hog_blocks_kernel(
    const float* __restrict__ cells, float* __restrict__ out)
{
    const int t = blockIdx.x * blockDim.x + threadIdx.x;
    const int g = t >> 3;           // HOG block index
    const int l = t & 7;            // lane within group
    const int total = B * NB * NB;
    if (g >= total) return;

    const int b  = g / (NB * NB);
    const int ij = g - b * (NB * NB);
    const int i  = ij / NB;
    const int j  = ij - i * NB;

    // lanes 0-3: cell row i (12 contiguous floats); lanes 4-7: row i+1
    const int row = i + (l >> 2);
    const int off = (l & 3) * 3;
    const float* p = cells + (((size_t)b * NC + row) * NC + j) * ORI + off;

    float v0 = __ldg(p);
    float v1 = __ldg(p + 1);
    float v2 = __ldg(p + 2);

    const float EPS2 = 1e-10f;  // (1e-5)^2

    float ss = v0 * v0 + v1 * v1 + v2 * v2;
    #pragma unroll
    for (int s = 4; s; s >>= 1) ss += __shfl_xor_sync(0xffffffffu, ss, s);
    const float inv_n1 = rsqrtf(ss + EPS2);
    v0 = fminf(v0 * inv_n1, 0.2f);
    v1 = fminf(v1 * inv_n1, 0.2f);
    v2 = fminf(v2 * inv_n1, 0.2f);

    float ss2 = v0 * v0 + v1 * v1 + v2 * v2;
    #pragma unroll
    for (int s = 4; s; s >>= 1) ss2 += __shfl_xor_sync(0xffffffffu, ss2, s);
    const float inv_n2 = rsqrtf(ss2 + EPS2);

    float* o = out + (size_t)g * BLK_FEAT + l * 3;
    o[0] = v0 * inv_n2;
    o[1] = v1 * inv_n2;
    o[2] = v2 * inv_n2;
}

// ---------------------------------------------------------------------------
extern "C" void kernel_launch(void* const* d_in, const int* in_sizes, int n_in,
                              void* d_out, int out_size)
{
    const float* x = (const float*)d_in[0];
    float* out = (float*)d_out;

    float* cells;
    cudaGetSymbolAddress((void**)&cells, g_cells);

    hog_cells_kernel<<<GRID_A, 512>>>(x, cells);

    const int total = B * NB * NB;                 // 30752
    const int threadsB = total * 8;
    hog_blocks_kernel<<<(threadsB + 255) / 256, 256>>>(cells, out);
}

// round 5
// speedup vs baseline: 1.1221x; 1.0560x over previous
#include <cuda_runtime.h>
#include <cuda_bf16.h>
#include <math.h>

#define H 512
#define W 512
#define B 32
#define CELL 16
#define NC 32            // cells per dim
#define NB 31            // blocks per dim
#define ORI 6
#define BLK_FEAT 24      // 2*2*ORI
#define HWsz (H*W)
#define NSTRIPS (B * NC) // 1024 jobs
#define GRID_A 592       // 148 SMs * 4 CTAs/SM (512thr, 36KB smem)

// scratch: per-cell histograms, (B, 32, 32, 6)
__device__ float g_cells[B * NC * NC * ORI];

// ---------------------------------------------------------------------------
// Phase 2 worker: gradients + binning + per-thread histograms.
// BORDER=false (interior strips): no per-pixel row checks at all.
// ---------------------------------------------------------------------------
template <bool BORDER>
__device__ __forceinline__ void phase2(
    const float (*sm)[512], int c, bool cok, int strip,
    float& h0, float& h1, float& h2, float& h3, float& h4, float& h5)
{
    const float C30 = 0.8660254037844386f;  // cos 30

    // rolling register window over own column: gr = sm[i+2][c] - sm[i][c]
    float w0 = sm[0][c];
    float w1 = sm[1][c];

    #pragma unroll
    for (int i = 0; i < 16; i++) {
        const float w2 = sm[i + 2][c];
        float gr = w2 - w0;
        if (BORDER) {
            const int r = strip * CELL + i;
            if (r == 0 || r == H - 1) gr = 0.0f;
        }
        const float gc = cok ? sm[i + 1][c + 1] - sm[i + 1][c - 1] : 0.0f;
        w0 = w1; w1 = w2;

        const float mag = sqrtf(gr * gr + gc * gc);

        // bin = floor((degrees(atan2(gr,gc)) mod 180)/30)
        // canonicalize to upper half-plane, then binary-search the sector:
        // hi = (angle >= 90); rotate by -90 if hi; 2 boundary tests remain.
        // Rotated tests are algebraically identical to the original >=120 and
        // >=150 cross-product tests (same float expressions), so semantics
        // match the 5-test version bit-exactly.
        float X = gc, Y = gr;
        if (Y < 0.0f || (Y == 0.0f && X < 0.0f)) { X = -X; Y = -Y; }
        const bool hi = (-X >= 0.0f);           // angle >= 90
        const float Xr = hi ?  Y : X;
        const float Yr = hi ? -X : Y;
        int bin = hi ? 3 : 0;
        bin += (C30  * Yr - 0.5f * Xr >= 0.0f); // >= 30 (or >= 120)
        bin += (0.5f * Yr - C30  * Xr >= 0.0f); // >= 60 (or >= 150)

        h0 += (bin == 0) ? mag : 0.0f;
        h1 += (bin == 1) ? mag : 0.0f;
        h2 += (bin == 2) ? mag : 0.0f;
        h3 += (bin == 3) ? mag : 0.0f;
        h4 += (bin == 4) ? mag : 0.0f;
        h5 += (bin == 5) ? mag : 0.0f;
    }
}

// ---------------------------------------------------------------------------
// Kernel A: persistent strip CTAs. Each 512-thread CTA grid-strides over
// (image, cell-row) jobs. Scalar coalesced loads, 18x512 smem gray strip,
// register histograms, 16-lane shfl reduction.
// ---------------------------------------------------------------------------
__global__ __launch_bounds__(512) void hog_cells_kernel(
    const float* __restrict__ x, float* __restrict__ cells)
{
    __shared__ float sm[18][512];
    const int c = threadIdx.x;      // column 0..511
    const bool cok = (c > 0) && (c < W - 1);

    for (int job = blockIdx.x; job < NSTRIPS; job += GRID_A) {
        const int strip = job & (NC - 1);   // cell row 0..31
        const int b     = job >> 5;         // image

        const float* xb = x + (size_t)b * 3 * HWsz;
        const int r0 = strip * CELL - 1;
        const bool border = (strip == 0) | (strip == NC - 1);

        __syncthreads();   // protect smem from previous iteration's readers

        if (!border) {
            // interior: all 18 rows valid, zero bounds checks, clean batching
            #pragma unroll
            for (int i = 0; i < 18; i++) {
                const int p = (r0 + i) * W + c;
                sm[i][c] = 0.299f * __ldg(xb + p)
                         + 0.587f * __ldg(xb + HWsz + p)
                         + 0.114f * __ldg(xb + 2 * HWsz + p);
            }
        } else {
            #pragma unroll
            for (int i = 0; i < 18; i++) {
                const int r = r0 + i;
                float g = 0.0f;
                if (r >= 0 && r < H) {
                    const int p = r * W + c;
                    g = 0.299f * __ldg(xb + p)
                      + 0.587f * __ldg(xb + HWsz + p)
                      + 0.114f * __ldg(xb + 2 * HWsz + p);
                }
                sm[i][c] = g;
            }
        }
        __syncthreads();

        float h0 = 0.f, h1 = 0.f, h2 = 0.f, h3 = 0.f, h4 = 0.f, h5 = 0.f;

        if (!border) phase2<false>(sm, c, cok, strip, h0, h1, h2, h3, h4, h5);
        else         phase2<true >(sm, c, cok, strip, h0, h1, h2, h3, h4, h5);

        // reduce across the 16 lanes of each column group
        #pragma unroll
        for (int s = 8; s; s >>= 1) {
            h0 += __shfl_xor_sync(0xffffffffu, h0, s);
            h1 += __shfl_xor_sync(0xffffffffu, h1, s);
            h2 += __shfl_xor_sync(0xffffffffu, h2, s);
            h3 += __shfl_xor_sync(0xffffffffu, h3, s);
            h4 += __shfl_xor_sync(0xffffffffu, h4, s);
            h5 += __shfl_xor_sync(0xffffffffu, h5, s);
        }

        if ((c & 15) == 0) {
            const int cellx = c >> 4;
            float* dst = cells + (((size_t)b * NC + strip) * NC + cellx) * ORI;
            const float inv = 1.0f / (CELL * CELL);
            dst[0] = h0 * inv;
            dst[1] = h1 * inv;
            dst[2] = h2 * inv;
            dst[3] = h3 * inv;
            dst[4] = h4 * inv;
            dst[5] = h5 * inv;
        }
    }

#if __CUDA_ARCH__ >= 900
    cudaTriggerProgrammaticLaunchCompletion();
#endif
}

// ---------------------------------------------------------------------------
// Kernel B: 8 lanes per HOG block; rsqrt-based L2-Hys. Launched with PDL so
// its ramp overlaps kernel A's tail; grid-dependency sync before reads.
// ---------------------------------------------------------------------------
__global__ __launch_bounds__(256) void hog_blocks_kernel(
    const float* __restrict__ cells, float* __restrict__ out)
{
#if __CUDA_ARCH__ >= 900
    cudaGridDependencySynchronize();
#endif

    const int t = blockIdx.x * blockDim.x + threadIdx.x;
    const int g = t >> 3;           // HOG block index
    const int l = t & 7;            // lane within group
    const int total = B * NB * NB;
    if (g >= total) return;

    const int b  = g / (NB * NB);
    const int ij = g - b * (NB * NB);
    const int i  = ij / NB;
    const int j  = ij - i * NB;

    // lanes 0-3: cell row i (12 contiguous floats); lanes 4-7: row i+1
    const int row = i + (l >> 2);
    const int off = (l & 3) * 3;
    const float* p = cells + (((size_t)b * NC + row) * NC + j) * ORI + off;

    float v0 = __ldg(p);
    float v1 = __ldg(p + 1);
    float v2 = __ldg(p + 2);

    const float EPS2 = 1e-10f;  // (1e-5)^2

    float ss = v0 * v0 + v1 * v1 + v2 * v2;
    #pragma unroll
    for (int s = 4; s; s >>= 1) ss += __shfl_xor_sync(0xffffffffu, ss, s);
    const float inv_n1 = rsqrtf(ss + EPS2);
    v0 = fminf(v0 * inv_n1, 0.2f);
    v1 = fminf(v1 * inv_n1, 0.2f);
    v2 = fminf(v2 * inv_n1, 0.2f);

    float ss2 = v0 * v0 + v1 * v1 + v2 * v2;
    #pragma unroll
    for (int s = 4; s; s >>= 1) ss2 += __shfl_xor_sync(0xffffffffu, ss2, s);
    const float inv_n2 = rsqrtf(ss2 + EPS2);

    float* o = out + (size_t)g * BLK_FEAT + l * 3;
    o[0] = v0 * inv_n2;
    o[1] = v1 * inv_n2;
    o[2] = v2 * inv_n2;
}

// ---------------------------------------------------------------------------
extern "C" void kernel_launch(void* const* d_in, const int* in_sizes, int n_in,
                              void* d_out, int out_size)
{
    const float* x = (const float*)d_in[0];
    float* out = (float*)d_out;

    float* cells;
    cudaGetSymbolAddress((void**)&cells, g_cells);

    hog_cells_kernel<<<GRID_A, 512>>>(x, cells);

    const int total = B * NB * NB;                 // 30752
    const int threadsB = total * 8;

    cudaLaunchConfig_t cfg = {};
    cfg.gridDim  = dim3((threadsB + 255) / 256);
    cfg.blockDim = dim3(256);
    cfg.dynamicSmemBytes = 0;
    cfg.stream = 0;
    cudaLaunchAttribute attrs[1];
    attrs[0].id = cudaLaunchAttributeProgrammaticStreamSerialization;
    attrs[0].val.programmaticStreamSerializationAllowed = 1;
    cfg.attrs = attrs;
    cfg.numAttrs = 1;
    cudaLaunchKernelEx(&cfg, hog_blocks_kernel, (const float*)cells, out);
}